// round 15
// baseline (speedup 1.0000x reference)
#include <cuda_runtime.h>

// Fixed problem shape
#define BB    256
#define TT    2048
#define HID   20
#define EMB   10
#define VOCAB 128

#define RING  128            // ring slots per row (power of 2)
#define TILE  32             // timesteps per publish/consume tile
#define NTILES (TT / TILE)   // 64 per row -> 128 consumer tiles per block
#define NCONS 2              // warps 0..1 consume; warp 2 produces (3 warps!)

typedef unsigned long long ull;

// ---- packed f32x2 helpers (FFMA2 — only reachable via PTX) --------------
__device__ __forceinline__ ull pk(float lo, float hi) {
    ull r; asm("mov.b64 %0, {%1,%2};" : "=l"(r) : "f"(lo), "f"(hi)); return r;
}
__device__ __forceinline__ void upk(float& lo, float& hi, ull v) {
    asm("mov.b64 {%0,%1}, %2;" : "=f"(lo), "=f"(hi) : "l"(v));
}
__device__ __forceinline__ void dfma(ull& d, ull a, ull b) {
    asm("fma.rn.f32x2 %0, %1, %2, %0;" : "+l"(d) : "l"(a), "l"(b));
}
__device__ __forceinline__ ull dadd(ull a, ull b) {
    ull r; asm("add.rn.f32x2 %0, %1, %2;" : "=l"(r) : "l"(a), "l"(b)); return r;
}
__device__ __forceinline__ float tanh_hw(float z) {
    float r; asm("tanh.approx.f32 %0, %1;" : "=f"(r) : "f"(z)); return r;
}

// ---------------------------------------------------------------------------
// One block per TWO batch rows, 96 threads (3 warps — below the nw>=4 smem
// crossbar binding point). Warp 2 (producer, alone on SMSP 2): two
// interleaved recurrences -> two smem rings. Warps 0-1 (consumers, SMSP 0/1):
// project finished 32-step tiles (both rows) to the 128-vocab output.
// Structure otherwise identical to the proven 199us R8 kernel.
// ---------------------------------------------------------------------------
__global__ void __launch_bounds__(96, 1) fused_rnn_kernel(
    const int*   __restrict__ inputs,
    const float* __restrict__ emb,
    const float* __restrict__ W_ih,
    const float* __restrict__ W_hh,
    const float* __restrict__ b_ih,
    const float* __restrict__ b_hh,
    const float* __restrict__ W_out,
    const float* __restrict__ b_out,
    float*       __restrict__ out)
{
    __shared__ __align__(16) float s_proj[VOCAB * HID];        // 10 KB
    __shared__ __align__(16) float s_ring[2][RING * HID];      // 2 x 10 KB
    __shared__ int s_idx[2][TILE];
    __shared__ volatile int s_prog;            // steps produced (both rows)
    __shared__ volatile int s_next[NCONS];     // next tile index per consumer

    const int tid  = threadIdx.x;
    const int lane = tid & 31;
    const int wid  = tid >> 5;
    const int b    = blockIdx.x;               // handles rows 2b, 2b+1

    // proj[v][j] = b_ih[j]+b_hh[j] + sum_e emb[v][e]*W_ih[j][e]
    for (int i = tid; i < VOCAB * HID; i += 96) {
        int v = i / HID, j = i - v * HID;
        float acc = b_ih[j] + b_hh[j];
#pragma unroll
        for (int e = 0; e < EMB; ++e)
            acc = fmaf(emb[v * EMB + e], W_ih[j * EMB + e], acc);
        s_proj[i] = acc;
    }
    if (tid == 0) s_prog = 0;
    if (tid < NCONS) s_next[tid] = tid;
    if (tid < HID) {
        s_ring[0][(RING - 1) * HID + tid] = 0.0f;   // h_{-1} = 0
        s_ring[1][(RING - 1) * HID + tid] = 0.0f;
    }
    __syncthreads();

    if (wid == NCONS) {
        // ================= PRODUCER (warp 2): two interleaved recurrences
        const int  j   = lane;
        const bool act = (j < HID);
        const int  jx  = act ? j : 0;

        ull w2[10];
        if (act) {
            const float4* wr = (const float4*)(W_hh + j * HID);
#pragma unroll
            for (int q = 0; q < 5; ++q) {
                float4 f = wr[q];
                w2[2*q]   = pk(f.x, f.y);
                w2[2*q+1] = pk(f.z, f.w);
            }
        } else {
#pragma unroll
            for (int q = 0; q < 10; ++q) w2[q] = 0ull;
        }

        const int* inp0 = inputs + (size_t)(2 * b + 0) * TT;
        const int* inp1 = inputs + (size_t)(2 * b + 1) * TT;

        // prologue: stage chunk-0 indices for both rows, prefetch x_0
        s_idx[0][lane] = inp0[lane];
        s_idx[1][lane] = inp1[lane];
        __syncwarp();
        float x0 = s_proj[s_idx[0][0] * HID + jx];
        float x1 = s_proj[s_idx[1][0] * HID + jx];

        for (int tc = 0; tc < TT; tc += TILE) {
            int ni0 = (tc + TILE < TT) ? inp0[tc + TILE + lane] : 0;
            int ni1 = (tc + TILE < TT) ? inp1[tc + TILE + lane] : 0;

            // back-pressure: both rows' ring slots [tc, tc+32) must be free.
            int needSteps = tc + TILE - RING;
            if (needSteps > 0) {
                int needTiles = (needSteps + TILE - 1) >> 5;
                if (lane == 0) {
                    for (;;) {
                        int m = s_next[0];
#pragma unroll
                        for (int k = 1; k < NCONS; ++k) m = min(m, s_next[k]);
                        if ((m >> 1) >= needTiles) break;
                        __nanosleep(128);
                    }
                }
                __syncwarp();
            }

#pragma unroll
            for (int tt = 0; tt < TILE; ++tt) {
                const int t    = tc + tt;
                const int rdsl = (t + RING - 1) & (RING - 1);
                const int wrsl = t & (RING - 1);

                // load h_{t-1} for both rows (independent -> overlapped)
                const ulonglong2* ha = (const ulonglong2*)(s_ring[0] + rdsl * HID);
                const ulonglong2* hb = (const ulonglong2*)(s_ring[1] + rdsl * HID);
                ulonglong2 a0 = ha[0], a1 = ha[1], a2 = ha[2], a3 = ha[3], a4 = ha[4];
                ulonglong2 b0 = hb[0], b1 = hb[1], b2 = hb[2], b3 = hb[3], b4 = hb[4];

                // prefetch next step's x for both rows (independent of chains)
                float nx0 = x0, nx1 = x1;
                if (tt < TILE - 1) {
                    nx0 = s_proj[s_idx[0][tt + 1] * HID + jx];
                    nx1 = s_proj[s_idx[1][tt + 1] * HID + jx];
                }

                // two independent matvecs, 4 FFMA2 chains each
                ull ca0 = pk(x0, 0.f), ca1 = pk(0.f,0.f), ca2 = pk(0.f,0.f), ca3 = pk(0.f,0.f);
                ull cb0 = pk(x1, 0.f), cb1 = pk(0.f,0.f), cb2 = pk(0.f,0.f), cb3 = pk(0.f,0.f);
                dfma(ca0, w2[0], a0.x); dfma(cb0, w2[0], b0.x);
                dfma(ca1, w2[1], a0.y); dfma(cb1, w2[1], b0.y);
                dfma(ca2, w2[2], a1.x); dfma(cb2, w2[2], b1.x);
                dfma(ca3, w2[3], a1.y); dfma(cb3, w2[3], b1.y);
                dfma(ca0, w2[4], a2.x); dfma(cb0, w2[4], b2.x);
                dfma(ca1, w2[5], a2.y); dfma(cb1, w2[5], b2.y);
                dfma(ca2, w2[6], a3.x); dfma(cb2, w2[6], b3.x);
                dfma(ca3, w2[7], a3.y); dfma(cb3, w2[7], b3.y);
                dfma(ca0, w2[8], a4.x); dfma(cb0, w2[8], b4.x);
                dfma(ca1, w2[9], a4.y); dfma(cb1, w2[9], b4.y);
                ull da = dadd(dadd(ca0, ca1), dadd(ca2, ca3));
                ull db = dadd(dadd(cb0, cb1), dadd(cb2, cb3));
                float la, hA; upk(la, hA, da);
                float lb, hB; upk(lb, hB, db);

                float hn0 = tanh_hw(la + hA);
                float hn1 = tanh_hw(lb + hB);
                if (act) {
                    s_ring[0][wrsl * HID + j] = hn0;
                    s_ring[1][wrsl * HID + j] = hn1;
                }
                x0 = nx0; x1 = nx1;
                // no per-step __syncwarp: same-warp STS->LDS is LSU-ordered
            }

            // publish superstep; stage next chunks' indices
            __syncwarp();
            __threadfence_block();
            if (lane == 0) s_prog = tc + TILE;
            s_idx[0][lane] = ni0;
            s_idx[1][lane] = ni1;
            __syncwarp();
            x0 = s_proj[s_idx[0][0] * HID + jx];
            x1 = s_proj[s_idx[1][0] * HID + jx];
        }
    } else {
        // ============ CONSUMERS (warps 0-1): tiles over {row} x {t-chunk}
        const int v0 = lane * 4;          // 32 lanes x 4 vocab = 128
        ull wo[4][10];
        ull bo[4];
#pragma unroll
        for (int r = 0; r < 4; ++r) {
            const float4* wr = (const float4*)(W_out + (v0 + r) * HID);
#pragma unroll
            for (int q = 0; q < 5; ++q) {
                float4 f = wr[q];
                wo[r][2*q]   = pk(f.x, f.y);
                wo[r][2*q+1] = pk(f.z, f.w);
            }
            bo[r] = pk(b_out[v0 + r], 0.0f);
        }

        for (int tl = wid; tl < 2 * NTILES; tl += NCONS) {
            const int row  = tl & 1;
            const int t0   = (tl >> 1) * TILE;
            const int tend = t0 + TILE;
            if (lane == 0) {
                while (s_prog < tend) __nanosleep(128);
            }
            __syncwarp();
            __threadfence_block();

            const float* ring = s_ring[row];
            float* outp = out + ((size_t)(2 * b + row) * TT + t0) * VOCAB + v0;
#pragma unroll 4
            for (int tt = 0; tt < TILE; ++tt) {
                const ulonglong2* hp = (const ulonglong2*)
                    (ring + ((t0 + tt) & (RING - 1)) * HID);
                ulonglong2 p0 = hp[0], p1 = hp[1], p2 = hp[2], p3 = hp[3], p4 = hp[4];

                float4 res;
#pragma unroll
                for (int r = 0; r < 4; ++r) {
                    ull acc = bo[r];
                    dfma(acc, wo[r][0], p0.x); dfma(acc, wo[r][1], p0.y);
                    dfma(acc, wo[r][2], p1.x); dfma(acc, wo[r][3], p1.y);
                    dfma(acc, wo[r][4], p2.x); dfma(acc, wo[r][5], p2.y);
                    dfma(acc, wo[r][6], p3.x); dfma(acc, wo[r][7], p3.y);
                    dfma(acc, wo[r][8], p4.x); dfma(acc, wo[r][9], p4.y);
                    float lo, hi; upk(lo, hi, acc);
                    (&res.x)[r] = lo + hi;
                }
                *(float4*)(outp + (size_t)tt * VOCAB) = res;   // 512B coalesced
            }
            __syncwarp();
            if (lane == 0) s_next[wid] = tl + NCONS;
        }
    }
}

// ---------------------------------------------------------------------------
// Inputs (metadata order):
// 0: inputs int32 [256,2048]  1: emb [128,10]  2: W_ih [20,10]  3: W_hh [20,20]
// 4: b_ih [20]  5: b_hh [20]  6: W_out [128,20]  7: b_out [128]
// Output: float32 [256,2048,128]
// ---------------------------------------------------------------------------
extern "C" void kernel_launch(void* const* d_in, const int* in_sizes, int n_in,
                              void* d_out, int out_size) {
    const int*   inputs = (const int*)d_in[0];
    const float* emb    = (const float*)d_in[1];
    const float* W_ih   = (const float*)d_in[2];
    const float* W_hh   = (const float*)d_in[3];
    const float* b_ih   = (const float*)d_in[4];
    const float* b_hh   = (const float*)d_in[5];
    const float* W_out  = (const float*)d_in[6];
    const float* b_out  = (const float*)d_in[7];
    float*       out    = (float*)d_out;

    fused_rnn_kernel<<<BB / 2, 96>>>(inputs, emb, W_ih, W_hh, b_ih, b_hh,
                                     W_out, b_out, out);
}

// round 16
// speedup vs baseline: 1.5253x; 1.5253x over previous
#include <cuda_runtime.h>

// Fixed problem shape
#define BB    256
#define TT    2048
#define HID   20
#define EMB   10
#define VOCAB 128

#define RING  128            // ring slots per row (power of 2)
#define TILE  32             // timesteps per publish/consume tile
#define NTILES (TT / TILE)   // 64 per row -> 128 consumer tiles per block
#define NCONS 3              // warps 0..2 consume; warp 3 produces

typedef unsigned long long ull;

// ---- packed f32x2 helpers (FFMA2 — only reachable via PTX) --------------
__device__ __forceinline__ ull pk(float lo, float hi) {
    ull r; asm("mov.b64 %0, {%1,%2};" : "=l"(r) : "f"(lo), "f"(hi)); return r;
}
__device__ __forceinline__ void upk(float& lo, float& hi, ull v) {
    asm("mov.b64 {%0,%1}, %2;" : "=f"(lo), "=f"(hi) : "l"(v));
}
__device__ __forceinline__ void dfma(ull& d, ull a, ull b) {
    asm("fma.rn.f32x2 %0, %1, %2, %0;" : "+l"(d) : "l"(a), "l"(b));
}
__device__ __forceinline__ ull dadd(ull a, ull b) {
    ull r; asm("add.rn.f32x2 %0, %1, %2;" : "=l"(r) : "l"(a), "l"(b)); return r;
}
__device__ __forceinline__ float tanh_hw(float z) {
    float r; asm("tanh.approx.f32 %0, %1;" : "=f"(r) : "f"(z)); return r;
}

// ---------------------------------------------------------------------------
// One block per TWO batch rows, 128 threads. (champion R8 structure)
// Warp 3 (producer): two interleaved recurrences -> two smem rings, with
//   chunk-peeled immediate ring addressing (zero per-step address ALU).
// Warps 0-2 (consumers): project finished 32-step tiles (both rows) to vocab.
// ---------------------------------------------------------------------------
__global__ void __launch_bounds__(128, 1) fused_rnn_kernel(
    const int*   __restrict__ inputs,
    const float* __restrict__ emb,
    const float* __restrict__ W_ih,
    const float* __restrict__ W_hh,
    const float* __restrict__ b_ih,
    const float* __restrict__ b_hh,
    const float* __restrict__ W_out,
    const float* __restrict__ b_out,
    float*       __restrict__ out)
{
    __shared__ __align__(16) float s_proj[VOCAB * HID];        // 10 KB
    __shared__ __align__(16) float s_ring[2][RING * HID];      // 2 x 10 KB
    __shared__ int s_idx[2][TILE];
    __shared__ volatile int s_prog;            // steps produced (both rows)
    __shared__ volatile int s_next[NCONS];     // next tile index per consumer

    const int tid  = threadIdx.x;
    const int lane = tid & 31;
    const int wid  = tid >> 5;
    const int b    = blockIdx.x;               // handles rows 2b, 2b+1

    // proj[v][j] = b_ih[j]+b_hh[j] + sum_e emb[v][e]*W_ih[j][e]
    for (int i = tid; i < VOCAB * HID; i += 128) {
        int v = i / HID, j = i - v * HID;
        float acc = b_ih[j] + b_hh[j];
#pragma unroll
        for (int e = 0; e < EMB; ++e)
            acc = fmaf(emb[v * EMB + e], W_ih[j * EMB + e], acc);
        s_proj[i] = acc;
    }
    if (tid == 0) s_prog = 0;
    if (tid < NCONS) s_next[tid] = tid;
    if (tid < HID) {
        s_ring[0][(RING - 1) * HID + tid] = 0.0f;   // h_{-1} = 0
        s_ring[1][(RING - 1) * HID + tid] = 0.0f;
    }
    __syncthreads();

    if (wid == NCONS) {
        // ================= PRODUCER (warp 3): two interleaved recurrences
        const int  j   = lane;
        const bool act = (j < HID);
        const int  jx  = act ? j : 0;

        ull w2[10];
        if (act) {
            const float4* wr = (const float4*)(W_hh + j * HID);
#pragma unroll
            for (int q = 0; q < 5; ++q) {
                float4 f = wr[q];
                w2[2*q]   = pk(f.x, f.y);
                w2[2*q+1] = pk(f.z, f.w);
            }
        } else {
#pragma unroll
            for (int q = 0; q < 10; ++q) w2[q] = 0ull;
        }

        const int* inp0 = inputs + (size_t)(2 * b + 0) * TT;
        const int* inp1 = inputs + (size_t)(2 * b + 1) * TT;

        // prologue: stage chunk-0 indices for both rows, prefetch x_0
        s_idx[0][lane] = inp0[lane];
        s_idx[1][lane] = inp1[lane];
        __syncwarp();
        float x0 = s_proj[s_idx[0][0] * HID + jx];
        float x1 = s_proj[s_idx[1][0] * HID + jx];

        for (int tc = 0; tc < TT; tc += TILE) {
            int ni0 = (tc + TILE < TT) ? inp0[tc + TILE + lane] : 0;
            int ni1 = (tc + TILE < TT) ? inp1[tc + TILE + lane] : 0;

            // back-pressure: both rows' ring slots [tc, tc+32) must be free.
            int needSteps = tc + TILE - RING;
            if (needSteps > 0) {
                int needTiles = (needSteps + TILE - 1) >> 5;
                if (lane == 0) {
                    for (;;) {
                        int m = s_next[0];
#pragma unroll
                        for (int k = 1; k < NCONS; ++k) m = min(m, s_next[k]);
                        if ((m >> 1) >= needTiles) break;
                        __nanosleep(128);
                    }
                }
                __syncwarp();
            }

            // Chunk-peeled addressing: slots tc..tc+31 are contiguous
            // (tc mod 128 in {0,32,64,96} -> no wrap inside a chunk); only
            // the tt=0 read of slot tc-1 can wrap. All per-step offsets are
            // compile-time immediates -> zero per-step address ALU.
            const int cb = tc & (RING - 1);
            const float* rpA = s_ring[0] + ((tc + RING - 1) & (RING - 1)) * HID;
            const float* rpB = s_ring[1] + ((tc + RING - 1) & (RING - 1)) * HID;
            const float* rbA = s_ring[0] + cb * HID;
            const float* rbB = s_ring[1] + cb * HID;
            float*       wbA = s_ring[0] + cb * HID + j;
            float*       wbB = s_ring[1] + cb * HID + j;

#pragma unroll
            for (int tt = 0; tt < TILE; ++tt) {
                // load h_{t-1} for both rows: immediate-offset LDS.128
                const ulonglong2* ha = (const ulonglong2*)
                    ((tt == 0) ? rpA : (rbA + (tt - 1) * HID));
                const ulonglong2* hb = (const ulonglong2*)
                    ((tt == 0) ? rpB : (rbB + (tt - 1) * HID));
                ulonglong2 a0 = ha[0], a1 = ha[1], a2 = ha[2], a3 = ha[3], a4 = ha[4];
                ulonglong2 b0 = hb[0], b1 = hb[1], b2 = hb[2], b3 = hb[3], b4 = hb[4];

                // prefetch next step's x for both rows (independent of chains)
                float nx0 = x0, nx1 = x1;
                if (tt < TILE - 1) {
                    nx0 = s_proj[s_idx[0][tt + 1] * HID + jx];
                    nx1 = s_proj[s_idx[1][tt + 1] * HID + jx];
                }

                // two independent matvecs, 4 FFMA2 chains each
                ull ca0 = pk(x0, 0.f), ca1 = pk(0.f,0.f), ca2 = pk(0.f,0.f), ca3 = pk(0.f,0.f);
                ull cb0 = pk(x1, 0.f), cb1 = pk(0.f,0.f), cb2 = pk(0.f,0.f), cb3 = pk(0.f,0.f);
                dfma(ca0, w2[0], a0.x); dfma(cb0, w2[0], b0.x);
                dfma(ca1, w2[1], a0.y); dfma(cb1, w2[1], b0.y);
                dfma(ca2, w2[2], a1.x); dfma(cb2, w2[2], b1.x);
                dfma(ca3, w2[3], a1.y); dfma(cb3, w2[3], b1.y);
                dfma(ca0, w2[4], a2.x); dfma(cb0, w2[4], b2.x);
                dfma(ca1, w2[5], a2.y); dfma(cb1, w2[5], b2.y);
                dfma(ca2, w2[6], a3.x); dfma(cb2, w2[6], b3.x);
                dfma(ca3, w2[7], a3.y); dfma(cb3, w2[7], b3.y);
                dfma(ca0, w2[8], a4.x); dfma(cb0, w2[8], b4.x);
                dfma(ca1, w2[9], a4.y); dfma(cb1, w2[9], b4.y);
                ull da = dadd(dadd(ca0, ca1), dadd(ca2, ca3));
                ull db = dadd(dadd(cb0, cb1), dadd(cb2, cb3));
                float la, hA; upk(la, hA, da);
                float lb, hB; upk(lb, hB, db);

                float hn0 = tanh_hw(la + hA);
                float hn1 = tanh_hw(lb + hB);
                if (act) {
                    wbA[tt * HID] = hn0;        // immediate-offset STS
                    wbB[tt * HID] = hn1;
                }
                x0 = nx0; x1 = nx1;
                // no per-step __syncwarp: same-warp STS->LDS is LSU-ordered
            }

            // publish superstep; stage next chunks' indices
            __syncwarp();
            __threadfence_block();
            if (lane == 0) s_prog = tc + TILE;
            s_idx[0][lane] = ni0;
            s_idx[1][lane] = ni1;
            __syncwarp();
            x0 = s_proj[s_idx[0][0] * HID + jx];
            x1 = s_proj[s_idx[1][0] * HID + jx];
        }
    } else {
        // ============ CONSUMERS (warps 0-2): tiles over {row} x {t-chunk}
        const int v0 = lane * 4;          // 32 lanes x 4 vocab = 128
        ull wo[4][10];
        ull bo[4];
#pragma unroll
        for (int r = 0; r < 4; ++r) {
            const float4* wr = (const float4*)(W_out + (v0 + r) * HID);
#pragma unroll
            for (int q = 0; q < 5; ++q) {
                float4 f = wr[q];
                wo[r][2*q]   = pk(f.x, f.y);
                wo[r][2*q+1] = pk(f.z, f.w);
            }
            bo[r] = pk(b_out[v0 + r], 0.0f);
        }

        for (int tl = wid; tl < 2 * NTILES; tl += NCONS) {
            const int row  = tl & 1;
            const int t0   = (tl >> 1) * TILE;
            const int tend = t0 + TILE;
            if (lane == 0) {
                while (s_prog < tend) __nanosleep(128);
            }
            __syncwarp();
            __threadfence_block();

            const float* ring = s_ring[row];
            float* outp = out + ((size_t)(2 * b + row) * TT + t0) * VOCAB + v0;
#pragma unroll 4
            for (int tt = 0; tt < TILE; ++tt) {
                const ulonglong2* hp = (const ulonglong2*)
                    (ring + ((t0 + tt) & (RING - 1)) * HID);
                ulonglong2 p0 = hp[0], p1 = hp[1], p2 = hp[2], p3 = hp[3], p4 = hp[4];

                float4 res;
#pragma unroll
                for (int r = 0; r < 4; ++r) {
                    ull acc = bo[r];
                    dfma(acc, wo[r][0], p0.x); dfma(acc, wo[r][1], p0.y);
                    dfma(acc, wo[r][2], p1.x); dfma(acc, wo[r][3], p1.y);
                    dfma(acc, wo[r][4], p2.x); dfma(acc, wo[r][5], p2.y);
                    dfma(acc, wo[r][6], p3.x); dfma(acc, wo[r][7], p3.y);
                    dfma(acc, wo[r][8], p4.x); dfma(acc, wo[r][9], p4.y);
                    float lo, hi; upk(lo, hi, acc);
                    (&res.x)[r] = lo + hi;
                }
                *(float4*)(outp + (size_t)tt * VOCAB) = res;   // 512B coalesced
            }
            __syncwarp();
            if (lane == 0) s_next[wid] = tl + NCONS;
        }
    }
}

// ---------------------------------------------------------------------------
// Inputs (metadata order):
// 0: inputs int32 [256,2048]  1: emb [128,10]  2: W_ih [20,10]  3: W_hh [20,20]
// 4: b_ih [20]  5: b_hh [20]  6: W_out [128,20]  7: b_out [128]
// Output: float32 [256,2048,128]
// ---------------------------------------------------------------------------
extern "C" void kernel_launch(void* const* d_in, const int* in_sizes, int n_in,
                              void* d_out, int out_size) {
    const int*   inputs = (const int*)d_in[0];
    const float* emb    = (const float*)d_in[1];
    const float* W_ih   = (const float*)d_in[2];
    const float* W_hh   = (const float*)d_in[3];
    const float* b_ih   = (const float*)d_in[4];
    const float* b_hh   = (const float*)d_in[5];
    const float* W_out  = (const float*)d_in[6];
    const float* b_out  = (const float*)d_in[7];
    float*       out    = (float*)d_out;

    fused_rnn_kernel<<<BB / 2, 128>>>(inputs, emb, W_ih, W_hh, b_ih, b_hh,
                                      W_out, b_out, out);
}